// round 6
// baseline (speedup 1.0000x reference)
#include <cuda_runtime.h>
#include <cstdint>

#define Bn 16
#define Cn 256
#define Ln 4096
#define Pn 100
#define Qn 20
#define TL 64              // l-tile
#define NW 16              // warps per block
#define KP 7               // p per warp: p = 7w + k (rows 100..111 zero-padded)
#define PPAD 112
#define NTILES (Bn * (Ln / TL))   // 1024
#define GRID 148           // persistent blocks, 1/SM
#define NTHR 512

__global__ void zero_cdf_kernel(float* out) {
    int i = blockIdx.x * 256 + threadIdx.x;
    if (i < Bn * Pn * Qn) out[i] = 0.0f;
}

__device__ __forceinline__ unsigned long long ffma2(unsigned long long a,
                                                    unsigned long long b,
                                                    unsigned long long c) {
    unsigned long long d;
    asm("fma.rn.f32x2 %0, %1, %2, %3;" : "=l"(d) : "l"(a), "l"(b), "l"(c));
    return d;
}
__device__ __forceinline__ unsigned long long pack2(float lo, float hi) {
    unsigned long long r;
    asm("mov.b64 %0, {%1,%2};" : "=l"(r) : "f"(lo), "f"(hi));
    return r;
}
__device__ __forceinline__ void unpack2(unsigned long long v, float& x, float& y) {
    asm("mov.b64 {%0,%1}, %2;" : "=f"(x), "=f"(y) : "l"(v));
}

__global__ __launch_bounds__(NTHR, 1)
void csf_persistent_kernel(const float* __restrict__ X,
                           const float* __restrict__ proj,
                           const float* __restrict__ minv,
                           const float* __restrict__ maxv,
                           float* __restrict__ out) {
    extern __shared__ float sm[];
    // Swizzled X tile: element (re, c) lives at word re*256 + (c ^ re).
    float* Xe  = sm;                 // [32][256]  l = 2*re
    float* Xo  = sm + 32 * 256;      // [32][256]  l = 2*re + 1
    float* pst = sm + 64 * 256;      // [PPAD][Cn], rows >= Pn zero
    float* thr = pst + PPAD * Cn;    // [Pn*Qn]

    const int tid  = threadIdx.x;
    const int w    = tid >> 5;
    const int lane = tid & 31;

    // ---- One-time staging: projections (zero-pad) + thresholds ----
    {
        const int total4 = PPAD * Cn / 4;          // 7168
        const int lim4   = Pn * Cn / 4;            // 6400
        for (int i = tid; i < total4; i += NTHR) {
            float4 v = make_float4(0.f, 0.f, 0.f, 0.f);
            if (i < lim4) v = ((const float4*)proj)[i];
            ((float4*)pst)[i] = v;
        }
        for (int i = tid; i < Pn * Qn; i += NTHR) {
            int p = i / Qn, q = i % Qn;
            float f = (float)(q + 1) / (float)(Qn + 1);
            thr[i] = minv[p] + (maxv[p] - minv[p]) * f;
        }
    }

    const int pbase = KP * w;                  // 7w
    const float* psb = pst + pbase * Cn;
    const int xw = lane * 256;                 // word base of this thread's rows

    for (int t = blockIdx.x; t < NTILES; t += GRID) {
        const int b  = t >> 6;
        const int l0 = (t & 63) * TL;

        // ---- Stage X tile (swizzled, conflict-free STS.32) ----
        {
            const float* Xb = X + (size_t)b * Cn * Ln + l0;
            #pragma unroll
            for (int j = 0; j < 8; j++) {
                int s  = j * NTHR + tid;        // 0..4095
                int c  = s >> 4;                // 0..255
                int l4 = (s & 15) * 4;          // 0,4,...,60
                float4 v = __ldcs((const float4*)(Xb + (size_t)c * Ln + l4));
                int re = l4 >> 1;               // even
                Xe[re * 256 + (c ^ re)]             = v.x;
                Xo[re * 256 + (c ^ re)]             = v.y;
                Xe[(re + 1) * 256 + (c ^ (re + 1))] = v.z;
                Xo[(re + 1) * 256 + (c ^ (re + 1))] = v.w;
            }
        }
        __syncthreads();

        // ---- Compute: warp w owns p = 7w..7w+6 (padded rows are zeros) ----
        unsigned long long acc0[KP], acc1[KP];
        #pragma unroll
        for (int k = 0; k < KP; k++) { acc0[k] = 0ull; acc1[k] = 0ull; }

        #pragma unroll 2
        for (int c = 0; c < Cn; c += 4) {
            int w0 = xw + ((c + 0) ^ lane);
            int w1 = xw + ((c + 1) ^ lane);
            int w2 = xw + ((c + 2) ^ lane);
            int w3 = xw + ((c + 3) ^ lane);
            unsigned long long xe01 = pack2(Xe[w0], Xe[w1]);
            unsigned long long xe23 = pack2(Xe[w2], Xe[w3]);
            unsigned long long xo01 = pack2(Xo[w0], Xo[w1]);
            unsigned long long xo23 = pack2(Xo[w2], Xo[w3]);
            #pragma unroll
            for (int k = 0; k < KP; k++) {
                ulonglong2 pv = *(const ulonglong2*)(psb + k * Cn + c);  // broadcast
                acc0[k] = ffma2(pv.x, xe01, acc0[k]);
                acc0[k] = ffma2(pv.y, xe23, acc0[k]);
                acc1[k] = ffma2(pv.x, xo01, acc1[k]);
                acc1[k] = ffma2(pv.y, xo23, acc1[k]);
            }
        }

        // ---- Epilogue: set stores + cdf counts ----
        float* cdfb = out + b * (Pn * Qn);
        float* setb = out + Bn * Pn * Qn + (size_t)b * Pn * Qn * Ln;

        #pragma unroll
        for (int k = 0; k < KP; k++) {
            const int p = pbase + k;
            if (p >= Pn) break;   // uniform within warp
            float e0, o0, e1, o1;
            unpack2(acc0[k], e0, o0);
            unpack2(acc1[k], e1, o1);
            float a0 = e0 + o0;   // l = l0 + 2*lane
            float a1 = e1 + o1;   // l = l0 + 2*lane + 1

            float2* dst = (float2*)(setb + (size_t)p * Qn * Ln + l0) + lane;
            const float* th = thr + p * Qn;

            #pragma unroll
            for (int qq = 0; qq < Qn; qq += 4) {
                unsigned packed = 0;
                #pragma unroll
                for (int j = 0; j < 4; j++) {
                    float tt = th[qq + j];
                    unsigned s0 = (a0 < tt) ? 1u : 0u;
                    unsigned s1 = (a1 < tt) ? 1u : 0u;
                    dst[(size_t)(qq + j) * (Ln / 2)] = make_float2((float)s0, (float)s1);
                    packed += (s0 + s1) << (8 * j);    // per-byte sum <= 64
                }
                unsigned r = __reduce_add_sync(0xffffffffu, packed);
                if (lane < 4) {
                    float v = (float)((r >> (8 * lane)) & 255u) * (1.0f / 4096.0f);
                    atomicAdd(cdfb + p * Qn + qq + lane, v);   // exact dyadic
                }
            }
        }
        __syncthreads();   // all warps done with Xs before next tile overwrites
    }
}

extern "C" void kernel_launch(void* const* d_in, const int* in_sizes, int n_in,
                              void* d_out, int out_size) {
    const float* X    = (const float*)d_in[0];
    const float* proj = (const float*)d_in[1];
    const float* minv = (const float*)d_in[2];
    const float* maxv = (const float*)d_in[3];
    float* out = (float*)d_out;

    zero_cdf_kernel<<<(Bn * Pn * Qn + 255) / 256, 256>>>(out);

    const int smem = (64 * 256 + PPAD * Cn + Pn * Qn) * (int)sizeof(float);
    cudaFuncSetAttribute(csf_persistent_kernel,
                         cudaFuncAttributeMaxDynamicSharedMemorySize, smem);
    csf_persistent_kernel<<<GRID, NTHR, smem>>>(X, proj, minv, maxv, out);
}

// round 7
// speedup vs baseline: 1.1513x; 1.1513x over previous
#include <cuda_runtime.h>
#include <cstdint>

#define Bn 16
#define Cn 256
#define Ln 4096
#define Pn 100
#define Qn 20
#define TL 64
#define SROW 260                 // word stride of Xe/Xo rows (1040B, 16B-aligned)
#define NW 12                    // warps per block
#define KP 9                     // p per warp: p = 9w + k (100..107 zero-padded)
#define PPAD (NW * KP)           // 108
#define NTILES (Bn * (Ln / TL))  // 1024
#define GRID 148
#define NTHR (NW * 32)           // 384
#define XO_OFF (32 * SROW + 16)  // Xo base: +16 words -> odd-lane STS banks disjoint

__global__ void zero_cdf_kernel(float* out) {
    int i = blockIdx.x * 256 + threadIdx.x;
    if (i < Bn * Pn * Qn) out[i] = 0.0f;
}

__device__ __forceinline__ unsigned long long ffma2(unsigned long long a,
                                                    unsigned long long b,
                                                    unsigned long long c) {
    unsigned long long d;
    asm("fma.rn.f32x2 %0, %1, %2, %3;" : "=l"(d) : "l"(a), "l"(b), "l"(c));
    return d;
}
__device__ __forceinline__ void unpack2(unsigned long long v, float& x, float& y) {
    asm("mov.b64 {%0,%1}, %2;" : "=f"(x), "=f"(y) : "l"(v));
}

// item = (cc, h): warp loads c = 4cc..4cc+3 for l = 32h + lane.
__device__ __forceinline__ float4 load_item(const float* Xb, int lane, int item) {
    int cc = item >> 1, h = item & 1;
    const float* s = Xb + (size_t)(4 * cc) * Ln + 32 * h + lane;
    float4 v;
    v.x = __ldcs(s);
    v.y = __ldcs(s + Ln);
    v.z = __ldcs(s + 2 * Ln);
    v.w = __ldcs(s + 3 * Ln);
    return v;
}
// STS.128: conflict-free per 8-lane phase (evens->Xe banks {0..15}+c0, odds->Xo {16..31}+c0)
__device__ __forceinline__ void stage_item(float* Xe, int lane, int item, float4 v) {
    int cc = item >> 1, h = item & 1;
    int r = 16 * h + (lane >> 1);
    float* base = Xe + ((lane & 1) ? XO_OFF : 0) + r * SROW + 4 * cc;
    *(float4*)base = v;
}

__global__ __launch_bounds__(NTHR, 1)
void csf_persistent_kernel(const float* __restrict__ X,
                           const float* __restrict__ proj,
                           const float* __restrict__ minv,
                           const float* __restrict__ maxv,
                           float* __restrict__ out) {
    extern __shared__ float sm[];
    float* Xe  = sm;                         // rows: l=2r; Xo at +XO_OFF: l=2r+1
    float* pst = sm + XO_OFF + 32 * SROW;    // [PPAD][Cn], rows >= Pn zero
    float* thr = pst + PPAD * Cn;            // [Pn*Qn]

    const int tid  = threadIdx.x;
    const int w    = tid >> 5;
    const int lane = tid & 31;

    // ---- One-time staging: projections (zero-pad) + thresholds ----
    {
        const int total4 = PPAD * Cn / 4;    // 6912
        const int lim4   = Pn * Cn / 4;      // 6400
        for (int i = tid; i < total4; i += NTHR) {
            float4 v = make_float4(0.f, 0.f, 0.f, 0.f);
            if (i < lim4) v = ((const float4*)proj)[i];
            ((float4*)pst)[i] = v;
        }
        for (int i = tid; i < Pn * Qn; i += NTHR) {
            int p = i / Qn, q = i % Qn;
            float f = (float)(q + 1) / (float)(Qn + 1);
            thr[i] = minv[p] + (maxv[p] - minv[p]) * f;
        }
    }

    const int pbase = KP * w;
    const float* psb = pst + pbase * Cn;
    const float* xa = Xe + lane * SROW;            // l = l0 + 2*lane
    const float* xb = Xe + XO_OFF + lane * SROW;   // l = l0 + 2*lane + 1

    int t = blockIdx.x;
    if (t >= NTILES) return;

    // Prologue: stage first tile directly (11 item rounds: 128 items over 12 warps).
    {
        const float* Xb = X + (size_t)(t >> 6) * Cn * Ln + (t & 63) * TL;
        #pragma unroll
        for (int j = 0; j < 11; j++) {
            int item = j * NW + w;
            if (item < 128) stage_item(Xe, lane, item, load_item(Xb, lane, item));
        }
    }
    __syncthreads();

    while (true) {
        const int b  = t >> 6;
        const int l0 = (t & 63) * TL;

        // ---- Compute: warp w owns p = 9w..9w+8 (padded rows are zeros) ----
        unsigned long long acc0[KP], acc1[KP];
        #pragma unroll
        for (int k = 0; k < KP; k++) { acc0[k] = 0ull; acc1[k] = 0ull; }

        #pragma unroll 2
        for (int c = 0; c < Cn; c += 4) {
            ulonglong2 x0 = *(const ulonglong2*)(xa + c);
            ulonglong2 x1 = *(const ulonglong2*)(xb + c);
            #pragma unroll
            for (int k = 0; k < KP; k++) {
                ulonglong2 pv = *(const ulonglong2*)(psb + k * Cn + c);  // broadcast
                acc0[k] = ffma2(pv.x, x0.x, acc0[k]);
                acc0[k] = ffma2(pv.y, x0.y, acc0[k]);
                acc1[k] = ffma2(pv.x, x1.x, acc1[k]);
                acc1[k] = ffma2(pv.y, x1.y, acc1[k]);
            }
        }

        // ---- Prefetch next tile (items 0..95 -> 32 regs); latency hidden by epilogue ----
        const int tn = t + GRID;
        const bool have = (tn < NTILES);
        float4 pf[8];
        const float* Xb2 = X + (size_t)(tn >> 6) * Cn * Ln + (tn & 63) * TL;
        if (have) {
            #pragma unroll
            for (int j = 0; j < 8; j++)
                pf[j] = load_item(Xb2, lane, j * NW + w);
        }

        // ---- Epilogue: set stores + cdf counts ----
        float* cdfb = out + b * (Pn * Qn);
        float* setb = out + Bn * Pn * Qn + (size_t)b * Pn * Qn * Ln;

        #pragma unroll
        for (int k = 0; k < KP; k++) {
            const int p = pbase + k;
            if (p >= Pn) break;   // uniform within warp (only warp 11)
            float e0, o0, e1, o1;
            unpack2(acc0[k], e0, o0);
            unpack2(acc1[k], e1, o1);
            float a0 = e0 + o0;   // l = l0 + 2*lane
            float a1 = e1 + o1;   // l = l0 + 2*lane + 1

            float2* dst = (float2*)(setb + (size_t)p * Qn * Ln + l0) + lane;
            const float* th = thr + p * Qn;

            #pragma unroll
            for (int qq = 0; qq < Qn; qq += 4) {
                unsigned packed = 0;
                #pragma unroll
                for (int j = 0; j < 4; j++) {
                    float tt = th[qq + j];
                    unsigned s0 = (a0 < tt) ? 1u : 0u;
                    unsigned s1 = (a1 < tt) ? 1u : 0u;
                    dst[(size_t)(qq + j) * (Ln / 2)] = make_float2((float)s0, (float)s1);
                    packed += (s0 + s1) << (8 * j);    // per-byte sum <= 64
                }
                unsigned r = __reduce_add_sync(0xffffffffu, packed);
                if (lane < 4) {
                    float v = (float)((r >> (8 * lane)) & 255u) * (1.0f / 4096.0f);
                    atomicAdd(cdfb + p * Qn + qq + lane, v);   // exact dyadic
                }
            }
        }

        if (!have) break;

        __syncthreads();   // all warps done reading Xe/Xo
        // Direct rounds for items 96..127 (issue LDGs first, overlap with pf STS)
        float4 dv[3];
        #pragma unroll
        for (int j = 8; j < 11; j++) {
            int item = j * NW + w;
            if (item < 128) dv[j - 8] = load_item(Xb2, lane, item);
        }
        #pragma unroll
        for (int j = 0; j < 8; j++)
            stage_item(Xe, lane, j * NW + w, pf[j]);
        #pragma unroll
        for (int j = 8; j < 11; j++) {
            int item = j * NW + w;
            if (item < 128) stage_item(Xe, lane, item, dv[j - 8]);
        }
        __syncthreads();   // tile ready

        t = tn;
    }
}

extern "C" void kernel_launch(void* const* d_in, const int* in_sizes, int n_in,
                              void* d_out, int out_size) {
    const float* X    = (const float*)d_in[0];
    const float* proj = (const float*)d_in[1];
    const float* minv = (const float*)d_in[2];
    const float* maxv = (const float*)d_in[3];
    float* out = (float*)d_out;

    zero_cdf_kernel<<<(Bn * Pn * Qn + 255) / 256, 256>>>(out);

    const int smem = (XO_OFF + 32 * SROW + PPAD * Cn + Pn * Qn) * (int)sizeof(float);
    cudaFuncSetAttribute(csf_persistent_kernel,
                         cudaFuncAttributeMaxDynamicSharedMemorySize, smem);
    csf_persistent_kernel<<<GRID, NTHR, smem>>>(X, proj, minv, maxv, out);
}